// round 6
// baseline (speedup 1.0000x reference)
#include <cuda_runtime.h>
#include <math.h>

#define SPLINE_ORDER 3
#define GRID_N   16
#define IN_DIM   64
#define OUT_DIM  64
#define BATCH    1024
#define NCOEF    (GRID_N + SPLINE_ORDER)   // 19

#define BT 32                 // batch tile (warp lanes = b)
#define OB 4                  // o-columns per block
#define THREADS 256

#define CS_FLOATS (OB * IN_DIM * NCOEF)    // 4864 floats (19456 B)
#define XS_FLOATS (BT * 65)                // 2080 floats ( 8320 B)
#define S4_FLOAT4 (OB * BT * 8)            // 1024 float4 (16384 B) half-i buffer
#define SMEM_BYTES ((CS_FLOATS + XS_FLOATS) * 4 + S4_FLOAT4 * 16)   // 44160

__global__ __launch_bounds__(THREADS, 5)
void kan_kernel(const float* __restrict__ x,
                const float* __restrict__ coef,
                const float* __restrict__ grid,
                float* __restrict__ out) {
    extern __shared__ float sm[];
    float*  cs = sm;                                    // coef tile [oo][i][19]
    float*  xs = sm + CS_FLOATS;                        // x tile [b][i], pitch 65
    float4* S4 = (float4*)(sm + CS_FLOATS + XS_FLOATS); // half transpose buf (swizzled)

    const int b0 = (blockIdx.x & 31) * BT;              // 32 batch tiles
    const int o0 = (blockIdx.x >> 5) * OB;              // 16 o-chunks
    const int lane = threadIdx.x & 31;                  // -> b
    const int warp = threadIdx.x >> 5;                  // -> i-quad within half

    // ---- Stage coef tile (contiguous float4) + x tile, both coalesced.
    {
        const float4* src = (const float4*)(coef + (size_t)o0 * IN_DIM * NCOEF);
        #pragma unroll
        for (int t = threadIdx.x; t < CS_FLOATS / 4; t += THREADS)
            ((float4*)cs)[t] = src[t];
        #pragma unroll
        for (int t = threadIdx.x; t < BT * IN_DIM; t += THREADS) {
            int bb = t >> 6, i = t & 63;
            xs[bb * 65 + i] = x[(b0 + bb) * IN_DIM + i];
        }
    }
    const float g3    = grid[SPLINE_ORDER];
    const float inv_h = 1.0f / (grid[SPLINE_ORDER + 1] - g3);
    const float k6    = 1.0f / 6.0f;
    __syncthreads();

    // ---- Two i-halves; weights computed once per half, reused for all 4 oo.
    #pragma unroll
    for (int g = 0; g < 2; g++) {
        const int ibase = g * 32 + warp * 4;

        float w0[4], w1[4], w2[4], w3[4];
        int   base[4];
        #pragma unroll
        for (int j = 0; j < 4; j++) {
            const float xv = xs[lane * 65 + ibase + j];
            float t = (xv - g3) * inv_h;
            int i0 = (int)floorf(t);
            i0 = min(GRID_N - 1, max(0, i0));
            const float u  = t - (float)i0;
            const float om = 1.0f - u;
            const float u2 = u * u;
            w0[j] = om * om * om * k6;
            w3[j] = u2 * u * k6;
            w1[j] = fmaf(u2, fmaf(0.5f, u, -1.0f), 2.0f / 3.0f);
            w2[j] = 1.0f - w0[j] - w1[j] - w3[j];
            base[j] = (ibase + j) * NCOEF + i0;
        }

        #pragma unroll
        for (int oo = 0; oo < OB; oo++) {
            const float* c = cs + oo * (IN_DIM * NCOEF);
            float4 r;
            // lanes=b: gather addrs in a 19-word window -> bank-conflict-free.
            r.x = fmaf(w3[0], c[base[0] + 3], fmaf(w2[0], c[base[0] + 2],
                  fmaf(w1[0], c[base[0] + 1], w0[0] * c[base[0]])));
            r.y = fmaf(w3[1], c[base[1] + 3], fmaf(w2[1], c[base[1] + 2],
                  fmaf(w1[1], c[base[1] + 1], w0[1] * c[base[1]])));
            r.z = fmaf(w3[2], c[base[2] + 3], fmaf(w2[2], c[base[2] + 2],
                  fmaf(w1[2], c[base[2] + 1], w0[2] * c[base[2]])));
            r.w = fmaf(w3[3], c[base[3] + 3], fmaf(w2[3], c[base[3] + 2],
                  fmaf(w1[3], c[base[3] + 1], w0[3] * c[base[3]])));
            // XOR-swizzled STS.128: bank group = warp ^ (lane&7) -> conflict-free.
            S4[oo * (BT * 8) + lane * 8 + (warp ^ (lane & 7))] = r;
        }
        __syncthreads();

        // ---- Store this i-half: 1024 float4, 4/thread, contiguous 128B half-rows.
        #pragma unroll
        for (int k = 0; k < 4; k++) {
            int t   = threadIdx.x + k * THREADS;
            int i4h = t & 7;
            int oo  = (t >> 3) & 3;
            int bb  = t >> 5;
            float4 v = S4[oo * (BT * 8) + bb * 8 + (i4h ^ (bb & 7))]; // conflict-free
            reinterpret_cast<float4*>(out)[
                ((size_t)(b0 + bb) * OUT_DIM + (o0 + oo)) * (IN_DIM / 4) + g * 8 + i4h] = v;
        }
        if (g == 0) __syncthreads();   // protect S4 reuse in half 2
    }
}

extern "C" void kernel_launch(void* const* d_in, const int* in_sizes, int n_in,
                              void* d_out, int out_size) {
    const float* x    = (const float*)d_in[0];
    const float* coef = (const float*)d_in[1];
    const float* grid = (const float*)d_in[2];
    float* out        = (float*)d_out;

    cudaFuncSetAttribute(kan_kernel, cudaFuncAttributeMaxDynamicSharedMemorySize,
                         SMEM_BYTES);
    kan_kernel<<<(BATCH / BT) * (OUT_DIM / OB), THREADS, SMEM_BYTES>>>(x, coef, grid, out);
}